// round 13
// baseline (speedup 1.0000x reference)
#include <cuda_runtime.h>
#include <cuda_fp16.h>
#include <cstdint>

#define BATCH 32
#define SEQ   2048
#define EDIM  1024
#define MROWS (BATCH * SEQ)   // 65536
#define NSC   16              // context S-split chunks

// ---------------- device scratch (no allocations allowed) ----------------
__device__ float g_qb[BATCH * EDIM];
__device__ float g_scores[BATCH * SEQ];
__device__ float g_attn[BATCH * SEQ];
__device__ float g_ctx_part[NSC * BATCH * EDIM];
__device__ __half g_a[(size_t)MROWS * EDIM];   // enc, fp16 (128 MB)
__device__ __half g_b[EDIM * EDIM];            // W1^T, fp16 [n][k]

// ---------------- PTX helpers (sm_80-compatible) ----------------
__device__ __forceinline__ uint32_t smem_u32(const void* p) {
    uint32_t a;
    asm("{ .reg .u64 t; cvta.to.shared.u64 t, %1; cvt.u32.u64 %0, t; }" : "=r"(a) : "l"(p));
    return a;
}
__device__ __forceinline__ void ldsm_x4(uint32_t* r, uint32_t addr) {
    asm volatile("ldmatrix.sync.aligned.m8n8.x4.shared.b16 {%0,%1,%2,%3}, [%4];"
                 : "=r"(r[0]), "=r"(r[1]), "=r"(r[2]), "=r"(r[3]) : "r"(addr));
}
__device__ __forceinline__ void mma_fp16(float* c, const uint32_t* a, const uint32_t* b) {
    asm volatile(
        "mma.sync.aligned.m16n8k16.row.col.f32.f16.f16.f32 "
        "{%0,%1,%2,%3}, {%4,%5,%6,%7}, {%8,%9}, {%0,%1,%2,%3};"
        : "+f"(c[0]), "+f"(c[1]), "+f"(c[2]), "+f"(c[3])
        : "r"(a[0]), "r"(a[1]), "r"(a[2]), "r"(a[3]), "r"(b[0]), "r"(b[1]));
}
__device__ __forceinline__ void cp16(uint32_t s, const void* g) {
    asm volatile("cp.async.cg.shared.global [%0], [%1], 16;" :: "r"(s), "l"(g));
}
#define CP_COMMIT() asm volatile("cp.async.commit_group;" ::: "memory")
#define CP_WAIT1()  asm volatile("cp.async.wait_group 1;" ::: "memory")
#define CP_WAIT0()  asm volatile("cp.async.wait_group 0;" ::: "memory")

__device__ __forceinline__ float fast_tanh(float x) {
    float e = __expf(2.0f * x);
    return 1.0f - 2.0f / (e + 1.0f);
}

// ---------------- K0a: convert enc -> fp16 ----------------
__global__ void conv_enc_kernel(const float* __restrict__ enc) {
    size_t base = ((size_t)blockIdx.x * 256 + threadIdx.x) * 8;
    float4 v0 = *reinterpret_cast<const float4*>(enc + base);
    float4 v1 = *reinterpret_cast<const float4*>(enc + base + 4);
    __half2 h[4];
    h[0] = __floats2half2_rn(v0.x, v0.y);
    h[1] = __floats2half2_rn(v0.z, v0.w);
    h[2] = __floats2half2_rn(v1.x, v1.y);
    h[3] = __floats2half2_rn(v1.z, v1.w);
    uint4 u;
    u.x = reinterpret_cast<uint32_t&>(h[0]); u.y = reinterpret_cast<uint32_t&>(h[1]);
    u.z = reinterpret_cast<uint32_t&>(h[2]); u.w = reinterpret_cast<uint32_t&>(h[3]);
    *reinterpret_cast<uint4*>(g_a + base) = u;
}

// ---------------- K0b: transpose + convert W1 -> B[n][k] fp16 ----------------
__global__ void conv_w1t_kernel(const float* __restrict__ w1) {
    __shared__ float t[32][33];
    int k0 = blockIdx.x * 32, n0 = blockIdx.y * 32;
    int tx = threadIdx.x, ty = threadIdx.y;
    t[ty][tx] = w1[(k0 + ty) * EDIM + n0 + tx];
    __syncthreads();
    g_b[(n0 + ty) * EDIM + k0 + tx] = __float2half_rn(t[tx][ty]);
}

// ---------------- K1: qb = dec@W2 + b2 + b1 ----------------
__global__ void qproj_kernel(const float* __restrict__ dec,
                             const float* __restrict__ w2,
                             const float* __restrict__ b2,
                             const float* __restrict__ b1) {
    __shared__ float sdec[EDIM];
    int b = blockIdx.x;
    int e = blockIdx.y * blockDim.x + threadIdx.x;
    for (int i = threadIdx.x; i < EDIM; i += blockDim.x)
        sdec[i] = dec[b * EDIM + i];
    __syncthreads();
    float acc = 0.f;
#pragma unroll 8
    for (int d = 0; d < EDIM; d++)
        acc += sdec[d] * w2[d * EDIM + e];
    g_qb[b * EDIM + e] = acc + b2[e] + b1[e];
}

// ---------------- K2: fp16 HMMA fused scores GEMM ----------------
// CTA tile 128(M) x 256(N), BK=64. Warp grid 2x4, warp tile 64x64 (acc=128 regs).
// 3-stage ring x { A 16K | B 32K } = 48KB/stage, occupancy 1, one barrier/stage.
#define STG_BYTES 49152
#define A_OFF 0
#define B_OFF 16384
#define QV_OFF  (3 * STG_BYTES)           // 147456
#define SCORES_SMEM (QV_OFF + 9 * 512)    // s_q[2][256] s_v[2][256] s_sc[128] -> 152064

// rows are 128B (64 halves), 8 chunks of 16B, full XOR swizzle
__device__ __forceinline__ uint32_t swz_off(int r, int kc) {
    return (uint32_t)(r * 128 + ((kc ^ (r & 7)) << 4));
}

__global__ __launch_bounds__(256, 1) void scores_mma_kernel(const float* __restrict__ v) {
    extern __shared__ char sm[];
    const uint32_t sb = smem_u32(sm);
    const int tid = threadIdx.x;
    const int lane = tid & 31, wid = tid >> 5;
    const int wy = wid >> 2, wn = wid & 3;       // 2 x 4 warp grid, 64x64 tiles
    const int m0 = blockIdx.x * 128;
    const int b  = m0 >> 11;

    float* s_q  = reinterpret_cast<float*>(sm + QV_OFF);        // [2][256]
    float* s_v  = s_q + 512;                                    // [2][256]
    float* s_sc = s_v + 512;                                    // [128]

    // ldmatrix lane invariants (mappings verified R5..R12)
    const int a_mi = (lane & 7) + ((lane >> 3) & 1) * 8;
    const int a_kc = lane >> 4;                   // 0/1
    int a_row[4], a_swz[4];
#pragma unroll
    for (int mt = 0; mt < 4; mt++) {
        int r = wy * 64 + mt * 16 + a_mi;
        a_row[mt] = r * 128;
        a_swz[mt] = r & 7;
    }
    const int b_ni = (lane & 7) + ((lane >> 4) & 1) * 8;
    const int b_kc = (lane >> 3) & 1;
    int b_row[4], b_swz[4];
#pragma unroll
    for (int p = 0; p < 4; p++) {
        int n = wn * 64 + p * 16 + b_ni;
        b_row[p] = n * 128;
        b_swz[p] = n & 7;
    }

    // loader for global stage gs (np = gs>>4, ks = gs&15) into ring buffer bufidx
    // A: 128 rows x 64 halves (chunks 0..1023), B: 256 rows (chunks 1024..3071)
    auto load_stage = [&](int gs, int bufidx) {
        const int n0 = (gs >> 4) * 256, k0 = (gs & 15) * 64;
        const uint32_t base = sb + bufidx * STG_BYTES;
#pragma unroll
        for (int i = 0; i < 4; i++) {            // A chunks
            int c = tid + i * 256;
            int row = c >> 3, kc = c & 7;
            cp16(base + A_OFF + swz_off(row, kc),
                 g_a + (size_t)(m0 + row) * EDIM + k0 + kc * 8);
        }
#pragma unroll
        for (int i = 0; i < 8; i++) {            // B chunks
            int c = tid + i * 256;               // 0..2047
            int row = c >> 3, kc = c & 7;
            cp16(base + B_OFF + swz_off(row, kc),
                 g_b + (size_t)(n0 + row) * EDIM + k0 + kc * 8);
        }
    };

    if (tid < 128) s_sc[tid] = 0.f;

    // prologue: stages 0 and 1 in flight (buffers 0, 1)
    load_stage(0, 0); CP_COMMIT();
    load_stage(1, 1); CP_COMMIT();

    int cbuf = 0;   // ring buffer being computed
    int lbuf = 2;   // ring buffer for next load

    for (int np = 0; np < 4; np++) {
        // double-buffered per-pass params (consumed in this np's epilogue)
        {
            const int n0 = np * 256;
            s_q[(np & 1) * 256 + tid] = g_qb[b * EDIM + n0 + tid];
            s_v[(np & 1) * 256 + tid] = v[n0 + tid];
        }

        float acc[4][8][4];                      // 64 x 64 per warp
#pragma unroll
        for (int mt = 0; mt < 4; mt++)
#pragma unroll
            for (int nt = 0; nt < 8; nt++)
#pragma unroll
                for (int r = 0; r < 4; r++) acc[mt][nt][r] = 0.f;

        for (int ks = 0; ks < 16; ks++) {
            const int gs = np * 16 + ks;

            if (gs == 63) { CP_WAIT0(); }        // tail: only stage 63 in flight
            else          { CP_WAIT1(); }        // stage gs complete (own copies)
            __syncthreads();                     // gs visible to all; all done with gs-1

            if (gs + 2 < 64) {                   // overwrites buffer of stage gs-1
                load_stage(gs + 2, lbuf);
                CP_COMMIT();
                lbuf = (lbuf == 2) ? 0 : lbuf + 1;
            }

            const uint32_t base = sb + cbuf * STG_BYTES;
#pragma unroll
            for (int kk = 0; kk < 4; kk++) {     // 4 x k16 within k64 stage
                uint32_t af[4][4];
#pragma unroll
                for (int mt = 0; mt < 4; mt++) {
                    uint32_t ao = (uint32_t)(a_row[mt] +
                        (((kk * 2 + a_kc) ^ a_swz[mt]) << 4));
                    ldsm_x4(af[mt], base + A_OFF + ao);
                }
#pragma unroll
                for (int p = 0; p < 4; p++) {
                    uint32_t bo = (uint32_t)(b_row[p] +
                        (((kk * 2 + b_kc) ^ b_swz[p]) << 4));
                    uint32_t bf[4];
                    ldsm_x4(bf, base + B_OFF + bo);
#pragma unroll
                    for (int mt = 0; mt < 4; mt++) {
                        mma_fp16(acc[mt][2 * p],     af[mt], bf);
                        mma_fp16(acc[mt][2 * p + 1], af[mt], bf + 2);
                    }
                }
            }
            cbuf = (cbuf == 2) ? 0 : cbuf + 1;
        }

        // epilogue: tanh(acc + q) . v  (rows wy*64 + mt*16 + lane>>2 (+8))
        {
            const float* q = s_q + (np & 1) * 256;
            const float* w = s_v + (np & 1) * 256;
            float part[8];
#pragma unroll
            for (int i = 0; i < 8; i++) part[i] = 0.f;
#pragma unroll
            for (int mt = 0; mt < 4; mt++)
#pragma unroll
                for (int nt = 0; nt < 8; nt++) {
                    int qi = wn * 64 + nt * 8 + 2 * (lane & 3);
                    float* c = acc[mt][nt];
                    part[mt * 2 + 0] += fast_tanh(c[0] + q[qi]) * w[qi]
                                      + fast_tanh(c[1] + q[qi + 1]) * w[qi + 1];
                    part[mt * 2 + 1] += fast_tanh(c[2] + q[qi]) * w[qi]
                                      + fast_tanh(c[3] + q[qi + 1]) * w[qi + 1];
                }
#pragma unroll
            for (int i = 0; i < 8; i++) {
                part[i] += __shfl_xor_sync(0xffffffffu, part[i], 1);
                part[i] += __shfl_xor_sync(0xffffffffu, part[i], 2);
            }
            if ((lane & 3) == 0) {
                int rbase = wy * 64 + (lane >> 2);
#pragma unroll
                for (int mt = 0; mt < 4; mt++) {
                    atomicAdd(&s_sc[rbase + mt * 16],     part[mt * 2 + 0]);
                    atomicAdd(&s_sc[rbase + mt * 16 + 8], part[mt * 2 + 1]);
                }
            }
        }
    }

    __syncthreads();   // all epilogue atomics done
    if (tid < 128) g_scores[m0 + tid] = s_sc[tid];
}

// ---------------- K3: softmax over S per batch ----------------
__global__ void softmax_kernel() {
    const int b = blockIdx.x;
    const int tid = threadIdx.x;
    const int lane = tid & 31, wid = tid >> 5;
    __shared__ float red[8];
    __shared__ float bcast;

    float vals[SEQ / 256];
#pragma unroll
    for (int i = 0; i < SEQ / 256; i++)
        vals[i] = g_scores[b * SEQ + i * 256 + tid];

    float m = vals[0];
#pragma unroll
    for (int i = 1; i < SEQ / 256; i++) m = fmaxf(m, vals[i]);
#pragma unroll
    for (int off = 16; off >= 1; off >>= 1)
        m = fmaxf(m, __shfl_xor_sync(0xffffffffu, m, off));
    if (lane == 0) red[wid] = m;
    __syncthreads();
    float bm = red[0];
#pragma unroll
    for (int w = 1; w < 8; w++) bm = fmaxf(bm, red[w]);
    __syncthreads();

    float sum = 0.f;
#pragma unroll
    for (int i = 0; i < SEQ / 256; i++) {
        vals[i] = __expf(vals[i] - bm);
        sum += vals[i];
    }
#pragma unroll
    for (int off = 16; off >= 1; off >>= 1)
        sum += __shfl_xor_sync(0xffffffffu, sum, off);
    if (lane == 0) red[wid] = sum;
    __syncthreads();
    if (tid == 0) {
        float t = 0.f;
#pragma unroll
        for (int w = 0; w < 8; w++) t += red[w];
        bcast = 1.0f / t;
    }
    __syncthreads();
    float inv = bcast;
#pragma unroll
    for (int i = 0; i < SEQ / 256; i++)
        g_attn[b * SEQ + i * 256 + tid] = vals[i] * inv;
}

// ---------------- K4a: context partials, fp16 enc (split-S, NSC chunks) ----------------
__global__ void context_part_kernel() {
    const int b = blockIdx.z;
    const int sc = blockIdx.y;
    const int e2 = blockIdx.x * 128 + threadIdx.x;   // half2 column index
    const int rows = SEQ / NSC;                      // 128
    const __half2* A = reinterpret_cast<const __half2*>(g_a)
                     + (size_t)(b * SEQ + sc * rows) * (EDIM / 2) + e2;
    const float* at = g_attn + b * SEQ + sc * rows;
    float ax = 0.f, ay = 0.f;
#pragma unroll 8
    for (int s = 0; s < rows; s++) {
        float w = at[s];
        float2 x = __half22float2(A[(size_t)s * (EDIM / 2)]);
        ax = fmaf(w, x.x, ax);
        ay = fmaf(w, x.y, ay);
    }
    float2* dst = reinterpret_cast<float2*>(
        g_ctx_part + ((size_t)sc * BATCH + b) * EDIM) + e2;
    *dst = make_float2(ax, ay);
}

// ---------------- K4b: sum partials ----------------
__global__ void context_sum_kernel(float* __restrict__ out) {
    const int i = blockIdx.x * 256 + threadIdx.x;
    float a = 0.f;
#pragma unroll
    for (int sc = 0; sc < NSC; sc++)
        a += g_ctx_part[(size_t)sc * BATCH * EDIM + i];
    out[i] = a;
}

// ---------------- launch ----------------
extern "C" void kernel_launch(void* const* d_in, const int* in_sizes, int n_in,
                              void* d_out, int out_size) {
    const float* enc = (const float*)d_in[0];
    const float* dec = (const float*)d_in[1];
    const float* w1  = (const float*)d_in[2];
    const float* b1  = (const float*)d_in[3];
    const float* w2  = (const float*)d_in[4];
    const float* b2  = (const float*)d_in[5];
    const float* v   = (const float*)d_in[6];
    // d_in[7] = bv: softmax-invariant, dropped
    float* out = (float*)d_out;

    cudaFuncSetAttribute(scores_mma_kernel,
                         cudaFuncAttributeMaxDynamicSharedMemorySize, SCORES_SMEM);

    conv_enc_kernel<<<(size_t)MROWS * EDIM / 2048, 256>>>(enc);
    conv_w1t_kernel<<<dim3(32, 32), dim3(32, 32)>>>(w1);
    qproj_kernel<<<dim3(BATCH, EDIM / 256), 256>>>(dec, w2, b2, b1);
    scores_mma_kernel<<<MROWS / 128, 256, SCORES_SMEM>>>(v);
    softmax_kernel<<<BATCH, 256>>>();
    context_part_kernel<<<dim3(EDIM / 256, NSC, BATCH), 128>>>();
    context_sum_kernel<<<BATCH * EDIM / 256, 256>>>(out);
}

// round 14
// speedup vs baseline: 1.0881x; 1.0881x over previous
#include <cuda_runtime.h>
#include <cuda_fp16.h>
#include <cstdint>

#define BATCH 32
#define SEQ   2048
#define EDIM  1024
#define MROWS (BATCH * SEQ)   // 65536
#define NSC   16              // context S-split chunks

// ---------------- device scratch (no allocations allowed) ----------------
__device__ float g_qb[BATCH * EDIM];
__device__ float g_scores[BATCH * SEQ];
__device__ float g_attn[BATCH * SEQ];
__device__ float g_ctx_part[NSC * BATCH * EDIM];
__device__ __half g_a[(size_t)MROWS * EDIM];   // enc, fp16 (128 MB)
__device__ __half g_b[EDIM * EDIM];            // W1^T, fp16 [n][k]

// ---------------- PTX helpers (sm_80-compatible) ----------------
__device__ __forceinline__ uint32_t smem_u32(const void* p) {
    uint32_t a;
    asm("{ .reg .u64 t; cvta.to.shared.u64 t, %1; cvt.u32.u64 %0, t; }" : "=r"(a) : "l"(p));
    return a;
}
__device__ __forceinline__ void ldsm_x4(uint32_t* r, uint32_t addr) {
    asm volatile("ldmatrix.sync.aligned.m8n8.x4.shared.b16 {%0,%1,%2,%3}, [%4];"
                 : "=r"(r[0]), "=r"(r[1]), "=r"(r[2]), "=r"(r[3]) : "r"(addr));
}
__device__ __forceinline__ void mma_fp16(float* c, const uint32_t* a, const uint32_t* b) {
    asm volatile(
        "mma.sync.aligned.m16n8k16.row.col.f32.f16.f16.f32 "
        "{%0,%1,%2,%3}, {%4,%5,%6,%7}, {%8,%9}, {%0,%1,%2,%3};"
        : "+f"(c[0]), "+f"(c[1]), "+f"(c[2]), "+f"(c[3])
        : "r"(a[0]), "r"(a[1]), "r"(a[2]), "r"(a[3]), "r"(b[0]), "r"(b[1]));
}
__device__ __forceinline__ void cp16(uint32_t s, const void* g) {
    asm volatile("cp.async.cg.shared.global [%0], [%1], 16;" :: "r"(s), "l"(g));
}
#define CP_COMMIT() asm volatile("cp.async.commit_group;" ::: "memory")
#define CP_WAIT1()  asm volatile("cp.async.wait_group 1;" ::: "memory")
#define CP_WAIT0()  asm volatile("cp.async.wait_group 0;" ::: "memory")

__device__ __forceinline__ float fast_tanh(float x) {
    float e = __expf(2.0f * x);
    return 1.0f - 2.0f / (e + 1.0f);
}

// ---------------- K0a: convert enc -> fp16 ----------------
__global__ void conv_enc_kernel(const float* __restrict__ enc) {
    size_t base = ((size_t)blockIdx.x * 256 + threadIdx.x) * 8;
    float4 v0 = *reinterpret_cast<const float4*>(enc + base);
    float4 v1 = *reinterpret_cast<const float4*>(enc + base + 4);
    __half2 h[4];
    h[0] = __floats2half2_rn(v0.x, v0.y);
    h[1] = __floats2half2_rn(v0.z, v0.w);
    h[2] = __floats2half2_rn(v1.x, v1.y);
    h[3] = __floats2half2_rn(v1.z, v1.w);
    uint4 u;
    u.x = reinterpret_cast<uint32_t&>(h[0]); u.y = reinterpret_cast<uint32_t&>(h[1]);
    u.z = reinterpret_cast<uint32_t&>(h[2]); u.w = reinterpret_cast<uint32_t&>(h[3]);
    *reinterpret_cast<uint4*>(g_a + base) = u;
}

// ---------------- K0b: transpose + convert W1 -> B[n][k] fp16 ----------------
__global__ void conv_w1t_kernel(const float* __restrict__ w1) {
    __shared__ float t[32][33];
    int k0 = blockIdx.x * 32, n0 = blockIdx.y * 32;
    int tx = threadIdx.x, ty = threadIdx.y;
    t[ty][tx] = w1[(k0 + ty) * EDIM + n0 + tx];
    __syncthreads();
    g_b[(n0 + ty) * EDIM + k0 + tx] = __float2half_rn(t[tx][ty]);
}

// ---------------- K1: qb = dec@W2 + b2 + b1 ----------------
__global__ void qproj_kernel(const float* __restrict__ dec,
                             const float* __restrict__ w2,
                             const float* __restrict__ b2,
                             const float* __restrict__ b1) {
    __shared__ float sdec[EDIM];
    int b = blockIdx.x;
    int e = blockIdx.y * blockDim.x + threadIdx.x;
    for (int i = threadIdx.x; i < EDIM; i += blockDim.x)
        sdec[i] = dec[b * EDIM + i];
    __syncthreads();
    float acc = 0.f;
#pragma unroll 8
    for (int d = 0; d < EDIM; d++)
        acc += sdec[d] * w2[d * EDIM + e];
    g_qb[b * EDIM + e] = acc + b2[e] + b1[e];
}

// ---------------- K2: fp16 HMMA fused scores GEMM ----------------
// CTA = 128 threads (2x2 warp grid), tile 128(M) x 128(N), BK=64.
// Warp tile 64x64 (ratio-4.0), 3-stage ring, 2 CTAs/SM, one barrier/stage.
#define STG_BYTES 32768
#define A_OFF 0
#define B_OFF 16384
#define QV_OFF  (3 * STG_BYTES)           // 98304
#define SCORES_SMEM (QV_OFF + 5 * 512)    // s_q[2][128] s_v[2][128] s_sc[128] -> 100864

// rows are 128B (64 halves), 8 chunks of 16B, full XOR swizzle
__device__ __forceinline__ uint32_t swz_off(int r, int kc) {
    return (uint32_t)(r * 128 + ((kc ^ (r & 7)) << 4));
}

__global__ __launch_bounds__(128, 2) void scores_mma_kernel(const float* __restrict__ v) {
    extern __shared__ char sm[];
    const uint32_t sb = smem_u32(sm);
    const int tid = threadIdx.x;
    const int lane = tid & 31, wid = tid >> 5;
    const int wy = wid >> 1, wn = wid & 1;       // 2 x 2 warp grid, 64x64 tiles
    const int m0 = blockIdx.x * 128;
    const int b  = m0 >> 11;

    float* s_q  = reinterpret_cast<float*>(sm + QV_OFF);        // [2][128]
    float* s_v  = s_q + 256;                                    // [2][128]
    float* s_sc = s_v + 256;                                    // [128]

    // ldmatrix lane invariants (mappings verified R5..R13)
    const int a_mi = (lane & 7) + ((lane >> 3) & 1) * 8;
    const int a_kc = lane >> 4;                   // 0/1
    int a_row[4], a_swz[4];
#pragma unroll
    for (int mt = 0; mt < 4; mt++) {
        int r = wy * 64 + mt * 16 + a_mi;
        a_row[mt] = r * 128;
        a_swz[mt] = r & 7;
    }
    const int b_ni = (lane & 7) + ((lane >> 4) & 1) * 8;
    const int b_kc = (lane >> 3) & 1;
    int b_row[4], b_swz[4];
#pragma unroll
    for (int p = 0; p < 4; p++) {
        int n = wn * 64 + p * 16 + b_ni;
        b_row[p] = n * 128;
        b_swz[p] = n & 7;
    }

    // loader for global stage gs (np = gs>>4, ks = gs&15) into ring buffer bufidx
    auto load_stage = [&](int gs, int bufidx) {
        const int n0 = (gs >> 4) * 128, k0 = (gs & 15) * 64;
        const uint32_t base = sb + bufidx * STG_BYTES;
#pragma unroll
        for (int i = 0; i < 8; i++) {            // A: 1024 chunks over 128 threads
            int c = tid + i * 128;
            int row = c >> 3, kc = c & 7;
            cp16(base + A_OFF + swz_off(row, kc),
                 g_a + (size_t)(m0 + row) * EDIM + k0 + kc * 8);
        }
#pragma unroll
        for (int i = 0; i < 8; i++) {            // B: 1024 chunks
            int c = tid + i * 128;
            int row = c >> 3, kc = c & 7;
            cp16(base + B_OFF + swz_off(row, kc),
                 g_b + (size_t)(n0 + row) * EDIM + k0 + kc * 8);
        }
    };

    s_sc[tid] = 0.f;

    // prologue: stages 0 and 1 in flight (buffers 0, 1)
    load_stage(0, 0); CP_COMMIT();
    load_stage(1, 1); CP_COMMIT();

    int cbuf = 0;   // ring buffer being computed
    int lbuf = 2;   // ring buffer for next load

    for (int np = 0; np < 8; np++) {
        // double-buffered per-pass params (consumed in this np's epilogue)
        {
            const int n0 = np * 128;
            s_q[(np & 1) * 128 + tid] = g_qb[b * EDIM + n0 + tid];
            s_v[(np & 1) * 128 + tid] = v[n0 + tid];
        }

        float acc[4][8][4];                      // 64 x 64 per warp
#pragma unroll
        for (int mt = 0; mt < 4; mt++)
#pragma unroll
            for (int nt = 0; nt < 8; nt++)
#pragma unroll
                for (int r = 0; r < 4; r++) acc[mt][nt][r] = 0.f;

        for (int ks = 0; ks < 16; ks++) {
            const int gs = np * 16 + ks;

            if (gs == 127) { CP_WAIT0(); }       // tail: only stage 127 in flight
            else           { CP_WAIT1(); }       // stage gs complete (own copies)
            __syncthreads();                     // gs visible to all; all done with gs-1

            if (gs + 2 < 128) {                  // overwrites buffer of stage gs-1
                load_stage(gs + 2, lbuf);
                CP_COMMIT();
                lbuf = (lbuf == 2) ? 0 : lbuf + 1;
            }

            const uint32_t base = sb + cbuf * STG_BYTES;
#pragma unroll
            for (int kk = 0; kk < 4; kk++) {     // 4 x k16 within k64 stage
                uint32_t af[4][4];
#pragma unroll
                for (int mt = 0; mt < 4; mt++) {
                    uint32_t ao = (uint32_t)(a_row[mt] +
                        (((kk * 2 + a_kc) ^ a_swz[mt]) << 4));
                    ldsm_x4(af[mt], base + A_OFF + ao);
                }
#pragma unroll
                for (int p = 0; p < 4; p++) {
                    uint32_t bo = (uint32_t)(b_row[p] +
                        (((kk * 2 + b_kc) ^ b_swz[p]) << 4));
                    uint32_t bf[4];
                    ldsm_x4(bf, base + B_OFF + bo);
#pragma unroll
                    for (int mt = 0; mt < 4; mt++) {
                        mma_fp16(acc[mt][2 * p],     af[mt], bf);
                        mma_fp16(acc[mt][2 * p + 1], af[mt], bf + 2);
                    }
                }
            }
            cbuf = (cbuf == 2) ? 0 : cbuf + 1;
        }

        // epilogue: tanh(acc + q) . v  (rows wy*64 + mt*16 + lane>>2 (+8))
        {
            const float* q = s_q + (np & 1) * 128;
            const float* w = s_v + (np & 1) * 128;
            float part[8];
#pragma unroll
            for (int i = 0; i < 8; i++) part[i] = 0.f;
#pragma unroll
            for (int mt = 0; mt < 4; mt++)
#pragma unroll
                for (int nt = 0; nt < 8; nt++) {
                    int qi = wn * 64 + nt * 8 + 2 * (lane & 3);
                    float* c = acc[mt][nt];
                    part[mt * 2 + 0] += fast_tanh(c[0] + q[qi]) * w[qi]
                                      + fast_tanh(c[1] + q[qi + 1]) * w[qi + 1];
                    part[mt * 2 + 1] += fast_tanh(c[2] + q[qi]) * w[qi]
                                      + fast_tanh(c[3] + q[qi + 1]) * w[qi + 1];
                }
#pragma unroll
            for (int i = 0; i < 8; i++) {
                part[i] += __shfl_xor_sync(0xffffffffu, part[i], 1);
                part[i] += __shfl_xor_sync(0xffffffffu, part[i], 2);
            }
            if ((lane & 3) == 0) {
                int rbase = wy * 64 + (lane >> 2);
#pragma unroll
                for (int mt = 0; mt < 4; mt++) {
                    atomicAdd(&s_sc[rbase + mt * 16],     part[mt * 2 + 0]);
                    atomicAdd(&s_sc[rbase + mt * 16 + 8], part[mt * 2 + 1]);
                }
            }
        }
    }

    __syncthreads();   // all epilogue atomics done
    g_scores[m0 + tid] = s_sc[tid];
}

// ---------------- K3: softmax over S per batch ----------------
__global__ void softmax_kernel() {
    const int b = blockIdx.x;
    const int tid = threadIdx.x;
    const int lane = tid & 31, wid = tid >> 5;
    __shared__ float red[8];
    __shared__ float bcast;

    float vals[SEQ / 256];
#pragma unroll
    for (int i = 0; i < SEQ / 256; i++)
        vals[i] = g_scores[b * SEQ + i * 256 + tid];

    float m = vals[0];
#pragma unroll
    for (int i = 1; i < SEQ / 256; i++) m = fmaxf(m, vals[i]);
#pragma unroll
    for (int off = 16; off >= 1; off >>= 1)
        m = fmaxf(m, __shfl_xor_sync(0xffffffffu, m, off));
    if (lane == 0) red[wid] = m;
    __syncthreads();
    float bm = red[0];
#pragma unroll
    for (int w = 1; w < 8; w++) bm = fmaxf(bm, red[w]);
    __syncthreads();

    float sum = 0.f;
#pragma unroll
    for (int i = 0; i < SEQ / 256; i++) {
        vals[i] = __expf(vals[i] - bm);
        sum += vals[i];
    }
#pragma unroll
    for (int off = 16; off >= 1; off >>= 1)
        sum += __shfl_xor_sync(0xffffffffu, sum, off);
    if (lane == 0) red[wid] = sum;
    __syncthreads();
    if (tid == 0) {
        float t = 0.f;
#pragma unroll
        for (int w = 0; w < 8; w++) t += red[w];
        bcast = 1.0f / t;
    }
    __syncthreads();
    float inv = bcast;
#pragma unroll
    for (int i = 0; i < SEQ / 256; i++)
        g_attn[b * SEQ + i * 256 + tid] = vals[i] * inv;
}

// ---------------- K4a: context partials, fp16 enc (split-S, NSC chunks) ----------------
__global__ void context_part_kernel() {
    const int b = blockIdx.z;
    const int sc = blockIdx.y;
    const int e2 = blockIdx.x * 128 + threadIdx.x;   // half2 column index
    const int rows = SEQ / NSC;                      // 128
    const __half2* A = reinterpret_cast<const __half2*>(g_a)
                     + (size_t)(b * SEQ + sc * rows) * (EDIM / 2) + e2;
    const float* at = g_attn + b * SEQ + sc * rows;
    float ax = 0.f, ay = 0.f;
#pragma unroll 8
    for (int s = 0; s < rows; s++) {
        float w = at[s];
        float2 x = __half22float2(A[(size_t)s * (EDIM / 2)]);
        ax = fmaf(w, x.x, ax);
        ay = fmaf(w, x.y, ay);
    }
    float2* dst = reinterpret_cast<float2*>(
        g_ctx_part + ((size_t)sc * BATCH + b) * EDIM) + e2;
    *dst = make_float2(ax, ay);
}

// ---------------- K4b: sum partials ----------------
__global__ void context_sum_kernel(float* __restrict__ out) {
    const int i = blockIdx.x * 256 + threadIdx.x;
    float a = 0.f;
#pragma unroll
    for (int sc = 0; sc < NSC; sc++)
        a += g_ctx_part[(size_t)sc * BATCH * EDIM + i];
    out[i] = a;
}

// ---------------- launch ----------------
extern "C" void kernel_launch(void* const* d_in, const int* in_sizes, int n_in,
                              void* d_out, int out_size) {
    const float* enc = (const float*)d_in[0];
    const float* dec = (const float*)d_in[1];
    const float* w1  = (const float*)d_in[2];
    const float* b1  = (const float*)d_in[3];
    const float* w2  = (const float*)d_in[4];
    const float* b2  = (const float*)d_in[5];
    const float* v   = (const float*)d_in[6];
    // d_in[7] = bv: softmax-invariant, dropped
    float* out = (float*)d_out;

    cudaFuncSetAttribute(scores_mma_kernel,
                         cudaFuncAttributeMaxDynamicSharedMemorySize, SCORES_SMEM);

    conv_enc_kernel<<<(size_t)MROWS * EDIM / 2048, 256>>>(enc);
    conv_w1t_kernel<<<dim3(32, 32), dim3(32, 32)>>>(w1);
    qproj_kernel<<<dim3(BATCH, EDIM / 256), 256>>>(dec, w2, b2, b1);
    scores_mma_kernel<<<MROWS / 128, 128, SCORES_SMEM>>>(v);
    softmax_kernel<<<BATCH, 256>>>();
    context_part_kernel<<<dim3(EDIM / 256, NSC, BATCH), 128>>>();
    context_sum_kernel<<<BATCH * EDIM / 256, 256>>>(out);
}

// round 15
// speedup vs baseline: 1.1736x; 1.0786x over previous
#include <cuda_runtime.h>
#include <cuda_fp16.h>
#include <cstdint>

#define BATCH 32
#define SEQ   2048
#define EDIM  1024
#define MROWS (BATCH * SEQ)   // 65536
#define NSC   16              // context S-split chunks

// ---------------- device scratch (no allocations allowed) ----------------
__device__ float g_qb[BATCH * EDIM];
__device__ float g_scores[BATCH * SEQ];
__device__ float g_attn[BATCH * SEQ];
__device__ float g_ctx_part[NSC * BATCH * EDIM];
__device__ __half g_a[(size_t)MROWS * EDIM];   // enc, fp16 (128 MB)
__device__ __half g_b[EDIM * EDIM];            // W1^T, fp16 [n][k]

// ---------------- PTX helpers ----------------
__device__ __forceinline__ uint32_t smem_u32(const void* p) {
    uint32_t a;
    asm("{ .reg .u64 t; cvta.to.shared.u64 t, %1; cvt.u32.u64 %0, t; }" : "=r"(a) : "l"(p));
    return a;
}
__device__ __forceinline__ void ldsm_x4(uint32_t* r, uint32_t addr) {
    asm volatile("ldmatrix.sync.aligned.m8n8.x4.shared.b16 {%0,%1,%2,%3}, [%4];"
                 : "=r"(r[0]), "=r"(r[1]), "=r"(r[2]), "=r"(r[3]) : "r"(addr));
}
__device__ __forceinline__ void mma_fp16(float* c, const uint32_t* a, const uint32_t* b) {
    asm volatile(
        "mma.sync.aligned.m16n8k16.row.col.f32.f16.f16.f32 "
        "{%0,%1,%2,%3}, {%4,%5,%6,%7}, {%8,%9}, {%0,%1,%2,%3};"
        : "+f"(c[0]), "+f"(c[1]), "+f"(c[2]), "+f"(c[3])
        : "r"(a[0]), "r"(a[1]), "r"(a[2]), "r"(a[3]), "r"(b[0]), "r"(b[1]));
}
__device__ __forceinline__ void cp16(uint32_t s, const void* g) {
    asm volatile("cp.async.cg.shared.global [%0], [%1], 16;" :: "r"(s), "l"(g));
}
#define CP_COMMIT() asm volatile("cp.async.commit_group;" ::: "memory")
#define CP_WAIT1()  asm volatile("cp.async.wait_group 1;" ::: "memory")
#define CP_WAIT0()  asm volatile("cp.async.wait_group 0;" ::: "memory")

#define MBAR_INIT(addr, cnt) \
    asm volatile("mbarrier.init.shared.b64 [%0], %1;" :: "r"(addr), "r"(cnt) : "memory")
#define MBAR_ARRIVE(addr) \
    asm volatile("mbarrier.arrive.shared.b64 _, [%0];" :: "r"(addr) : "memory")
__device__ __forceinline__ void mbar_wait(uint32_t addr, uint32_t parity) {
    asm volatile(
        "{\n\t.reg .pred P;\n\t"
        "WL_%=:\n\t"
        "mbarrier.try_wait.parity.acquire.cta.shared::cta.b64 P, [%0], %1, 0x989680;\n\t"
        "@!P bra WL_%=;\n\t}"
        :: "r"(addr), "r"(parity) : "memory");
}

__device__ __forceinline__ float fast_tanh(float x) {
    float e = __expf(2.0f * x);
    return 1.0f - 2.0f / (e + 1.0f);
}

// ---------------- K0a: convert enc -> fp16 ----------------
__global__ void conv_enc_kernel(const float* __restrict__ enc) {
    size_t base = ((size_t)blockIdx.x * 256 + threadIdx.x) * 8;
    float4 v0 = *reinterpret_cast<const float4*>(enc + base);
    float4 v1 = *reinterpret_cast<const float4*>(enc + base + 4);
    __half2 h[4];
    h[0] = __floats2half2_rn(v0.x, v0.y);
    h[1] = __floats2half2_rn(v0.z, v0.w);
    h[2] = __floats2half2_rn(v1.x, v1.y);
    h[3] = __floats2half2_rn(v1.z, v1.w);
    uint4 u;
    u.x = reinterpret_cast<uint32_t&>(h[0]); u.y = reinterpret_cast<uint32_t&>(h[1]);
    u.z = reinterpret_cast<uint32_t&>(h[2]); u.w = reinterpret_cast<uint32_t&>(h[3]);
    *reinterpret_cast<uint4*>(g_a + base) = u;
}

// ---------------- K0b: transpose + convert W1 -> B[n][k] fp16 ----------------
__global__ void conv_w1t_kernel(const float* __restrict__ w1) {
    __shared__ float t[32][33];
    int k0 = blockIdx.x * 32, n0 = blockIdx.y * 32;
    int tx = threadIdx.x, ty = threadIdx.y;
    t[ty][tx] = w1[(k0 + ty) * EDIM + n0 + tx];
    __syncthreads();
    g_b[(n0 + ty) * EDIM + k0 + tx] = __float2half_rn(t[tx][ty]);
}

// ---------------- K1: qb = dec@W2 + b2 + b1 ----------------
__global__ void qproj_kernel(const float* __restrict__ dec,
                             const float* __restrict__ w2,
                             const float* __restrict__ b2,
                             const float* __restrict__ b1) {
    __shared__ float sdec[EDIM];
    int b = blockIdx.x;
    int e = blockIdx.y * blockDim.x + threadIdx.x;
    for (int i = threadIdx.x; i < EDIM; i += blockDim.x)
        sdec[i] = dec[b * EDIM + i];
    __syncthreads();
    float acc = 0.f;
#pragma unroll 8
    for (int d = 0; d < EDIM; d++)
        acc += sdec[d] * w2[d * EDIM + e];
    g_qb[b * EDIM + e] = acc + b2[e] + b1[e];
}

// ---------------- K2: fp16 HMMA fused scores GEMM ----------------
// R12 champion geometry (256 thr, 4x2 warps of 32x64, BM=128, BN=128, BK=64,
// 3-stage ring, 2 CTAs/SM) with mbarrier full/empty pipeline instead of
// lockstep __syncthreads — warps may drift up to ~3 stages.
#define STG_BYTES 32768
#define A_OFF 0
#define B_OFF 16384
#define QV_OFF  (3 * STG_BYTES)               // 98304
#define MB_OFF  (QV_OFF + 2560)               // after s_q/s_v/s_sc
#define SCORES_SMEM (MB_OFF + 64)             // 100928

// rows are 128B (64 halves), 8 chunks of 16B, full XOR swizzle
__device__ __forceinline__ uint32_t swz_off(int r, int kc) {
    return (uint32_t)(r * 128 + ((kc ^ (r & 7)) << 4));
}

__global__ __launch_bounds__(256, 2) void scores_mma_kernel(const float* __restrict__ v) {
    extern __shared__ char sm[];
    const uint32_t sb = smem_u32(sm);
    const int tid = threadIdx.x;
    const int lane = tid & 31, wid = tid >> 5;
    const int wy = wid >> 1, wn = wid & 1;       // 4 x 2 warp grid, 32x64 tiles
    const int m0 = blockIdx.x * 128;
    const int b  = m0 >> 11;

    float* s_q  = reinterpret_cast<float*>(sm + QV_OFF);        // [2][128]
    float* s_v  = s_q + 256;                                    // [2][128]
    float* s_sc = s_v + 256;                                    // [128]
    const uint32_t mb_full  = sb + MB_OFF;       // 3 x 8B
    const uint32_t mb_empty = sb + MB_OFF + 24;  // 3 x 8B

    // ldmatrix lane invariants (verified R5..R12)
    const int a_mi = (lane & 7) + ((lane >> 3) & 1) * 8;
    const int a_kc = lane >> 4;                   // 0/1
    int a_row[2], a_swz[2];
#pragma unroll
    for (int mt = 0; mt < 2; mt++) {
        int r = wy * 32 + mt * 16 + a_mi;
        a_row[mt] = r * 128;
        a_swz[mt] = r & 7;
    }
    const int b_ni = (lane & 7) + ((lane >> 4) & 1) * 8;
    const int b_kc = (lane >> 3) & 1;
    int b_row[4], b_swz[4];
#pragma unroll
    for (int p = 0; p < 4; p++) {
        int n = wn * 64 + p * 16 + b_ni;
        b_row[p] = n * 128;
        b_swz[p] = n & 7;
    }

    // loader for global stage gs (np = gs>>4, ks = gs&15) into ring buffer bufidx
    auto load_stage = [&](int gs, int bufidx) {
        const int n0 = (gs >> 4) * 128, k0 = (gs & 15) * 64;
        const uint32_t base = sb + bufidx * STG_BYTES;
#pragma unroll
        for (int i = 0; i < 4; i++) {
            int c = tid + i * 256;               // 0..1023
            int row = c >> 3, kc = c & 7;
            uint32_t so = swz_off(row, kc);
            size_t ga = (size_t)(m0 + row) * EDIM + k0 + kc * 8;
            size_t gb = (size_t)(n0 + row) * EDIM + k0 + kc * 8;
            cp16(base + A_OFF + so, g_a + ga);
            cp16(base + B_OFF + so, g_b + gb);
        }
    };

    if (tid < 128) s_sc[tid] = 0.f;
    if (tid == 0) {
#pragma unroll
        for (int i = 0; i < 3; i++) {
            MBAR_INIT(mb_full + i * 8, 256);     // every thread arrives per stage
            MBAR_INIT(mb_empty + i * 8, 8);      // one arrive per warp per stage
        }
    }
    __syncthreads();   // mbarriers + s_sc visible

    // prologue: stages 0 and 1 in flight (buffers 0, 1)
    load_stage(0, 0); CP_COMMIT();
    load_stage(1, 1); CP_COMMIT();

    int cbuf = 0, fp = 0;   // compute buffer + full-phase (flips when cbuf wraps)
    int lbuf = 2, ep = 0;   // load buffer + empty-phase (flips after waiting buf 2)

    for (int np = 0; np < 8; np++) {
        // double-buffered per-pass params (consumed in this np's epilogue;
        // parity-safe: warp drift bounded by empty backpressure << 17 stages)
        if (tid < 128) {
            const int n0 = np * 128;
            s_q[(np & 1) * 128 + tid] = g_qb[b * EDIM + n0 + tid];
            s_v[(np & 1) * 128 + tid] = v[n0 + tid];
        }

        float acc[2][8][4];
#pragma unroll
        for (int mt = 0; mt < 2; mt++)
#pragma unroll
            for (int nt = 0; nt < 8; nt++)
#pragma unroll
                for (int r = 0; r < 4; r++) acc[mt][nt][r] = 0.f;

        for (int ks = 0; ks < 16; ks++) {
            const int gs = np * 16 + ks;

            // A: own loads of stage gs complete -> announce to full[cbuf]
            if (gs == 127) { CP_WAIT0(); } else { CP_WAIT1(); }
            MBAR_ARRIVE(mb_full + cbuf * 8);

            // B: backpressure on ring reuse, then issue loads for gs+2
            if (gs + 2 < 128) {
                if (gs >= 1) {                   // first use of each buffer skips
                    mbar_wait(mb_empty + lbuf * 8, (uint32_t)ep);
                    if (lbuf == 2) ep ^= 1;
                }
                load_stage(gs + 2, lbuf);
                CP_COMMIT();
                lbuf = (lbuf == 2) ? 0 : lbuf + 1;
            }

            // C: wait all threads' loads of gs, compute, release buffer
            mbar_wait(mb_full + cbuf * 8, (uint32_t)fp);

            const uint32_t base = sb + cbuf * STG_BYTES;
#pragma unroll
            for (int kk = 0; kk < 4; kk++) {     // 4 x k16 within k64 stage
                uint32_t af[2][4];
#pragma unroll
                for (int mt = 0; mt < 2; mt++) {
                    uint32_t ao = (uint32_t)(a_row[mt] +
                        (((kk * 2 + a_kc) ^ a_swz[mt]) << 4));
                    ldsm_x4(af[mt], base + A_OFF + ao);
                }
#pragma unroll
                for (int p = 0; p < 4; p++) {
                    uint32_t bo = (uint32_t)(b_row[p] +
                        (((kk * 2 + b_kc) ^ b_swz[p]) << 4));
                    uint32_t bf[4];
                    ldsm_x4(bf, base + B_OFF + bo);
#pragma unroll
                    for (int mt = 0; mt < 2; mt++) {
                        mma_fp16(acc[mt][2 * p],     af[mt], bf);
                        mma_fp16(acc[mt][2 * p + 1], af[mt], bf + 2);
                    }
                }
            }
            if (lane == 0) MBAR_ARRIVE(mb_empty + cbuf * 8);
            if (cbuf == 2) { cbuf = 0; fp ^= 1; } else { cbuf++; }
        }

        // epilogue: tanh(acc + q) . v
        {
            const float* q = s_q + (np & 1) * 128;
            const float* w = s_v + (np & 1) * 128;
            float part[4] = {0.f, 0.f, 0.f, 0.f};
#pragma unroll
            for (int mt = 0; mt < 2; mt++)
#pragma unroll
                for (int nt = 0; nt < 8; nt++) {
                    int qi = wn * 64 + nt * 8 + 2 * (lane & 3);
                    float* c = acc[mt][nt];
                    part[mt * 2 + 0] += fast_tanh(c[0] + q[qi]) * w[qi]
                                      + fast_tanh(c[1] + q[qi + 1]) * w[qi + 1];
                    part[mt * 2 + 1] += fast_tanh(c[2] + q[qi]) * w[qi]
                                      + fast_tanh(c[3] + q[qi + 1]) * w[qi + 1];
                }
#pragma unroll
            for (int i = 0; i < 4; i++) {
                part[i] += __shfl_xor_sync(0xffffffffu, part[i], 1);
                part[i] += __shfl_xor_sync(0xffffffffu, part[i], 2);
            }
            if ((lane & 3) == 0) {
                int rbase = wy * 32 + (lane >> 2);
                atomicAdd(&s_sc[rbase],      part[0]);
                atomicAdd(&s_sc[rbase + 8],  part[1]);
                atomicAdd(&s_sc[rbase + 16], part[2]);
                atomicAdd(&s_sc[rbase + 24], part[3]);
            }
        }
    }

    __syncthreads();   // all epilogue atomics done
    if (tid < 128) g_scores[m0 + tid] = s_sc[tid];
}

// ---------------- K3: softmax over S per batch ----------------
__global__ void softmax_kernel() {
    const int b = blockIdx.x;
    const int tid = threadIdx.x;
    const int lane = tid & 31, wid = tid >> 5;
    __shared__ float red[8];
    __shared__ float bcast;

    float vals[SEQ / 256];
#pragma unroll
    for (int i = 0; i < SEQ / 256; i++)
        vals[i] = g_scores[b * SEQ + i * 256 + tid];

    float m = vals[0];
#pragma unroll
    for (int i = 1; i < SEQ / 256; i++) m = fmaxf(m, vals[i]);
#pragma unroll
    for (int off = 16; off >= 1; off >>= 1)
        m = fmaxf(m, __shfl_xor_sync(0xffffffffu, m, off));
    if (lane == 0) red[wid] = m;
    __syncthreads();
    float bm = red[0];
#pragma unroll
    for (int w = 1; w < 8; w++) bm = fmaxf(bm, red[w]);
    __syncthreads();

    float sum = 0.f;
#pragma unroll
    for (int i = 0; i < SEQ / 256; i++) {
        vals[i] = __expf(vals[i] - bm);
        sum += vals[i];
    }
#pragma unroll
    for (int off = 16; off >= 1; off >>= 1)
        sum += __shfl_xor_sync(0xffffffffu, sum, off);
    if (lane == 0) red[wid] = sum;
    __syncthreads();
    if (tid == 0) {
        float t = 0.f;
#pragma unroll
        for (int w = 0; w < 8; w++) t += red[w];
        bcast = 1.0f / t;
    }
    __syncthreads();
    float inv = bcast;
#pragma unroll
    for (int i = 0; i < SEQ / 256; i++)
        g_attn[b * SEQ + i * 256 + tid] = vals[i] * inv;
}

// ---------------- K4a: context partials, fp16 enc (split-S, NSC chunks) ----------------
__global__ void context_part_kernel() {
    const int b = blockIdx.z;
    const int sc = blockIdx.y;
    const int e2 = blockIdx.x * 128 + threadIdx.x;   // half2 column index
    const int rows = SEQ / NSC;                      // 128
    const __half2* A = reinterpret_cast<const __half2*>(g_a)
                     + (size_t)(b * SEQ + sc * rows) * (EDIM / 2) + e2;
    const float* at = g_attn + b * SEQ + sc * rows;
    float ax = 0.f, ay = 0.f;
#pragma unroll 8
    for (int s = 0; s < rows; s++) {
        float w = at[s];
        float2 x = __half22float2(A[(size_t)s * (EDIM / 2)]);
        ax = fmaf(w, x.x, ax);
        ay = fmaf(w, x.y, ay);
    }
    float2* dst = reinterpret_cast<float2*>(
        g_ctx_part + ((size_t)sc * BATCH + b) * EDIM) + e2;
    *dst = make_float2(ax, ay);
}

// ---------------- K4b: sum partials ----------------
__global__ void context_sum_kernel(float* __restrict__ out) {
    const int i = blockIdx.x * 256 + threadIdx.x;
    float a = 0.f;
#pragma unroll
    for (int sc = 0; sc < NSC; sc++)
        a += g_ctx_part[(size_t)sc * BATCH * EDIM + i];
    out[i] = a;
}

// ---------------- launch ----------------
extern "C" void kernel_launch(void* const* d_in, const int* in_sizes, int n_in,
                              void* d_out, int out_size) {
    const float* enc = (const float*)d_in[0];
    const float* dec = (const float*)d_in[1];
    const float* w1  = (const float*)d_in[2];
    const float* b1  = (const float*)d_in[3];
    const float* w2  = (const float*)d_in[4];
    const float* b2  = (const float*)d_in[5];
    const float* v   = (const float*)d_in[6];
    // d_in[7] = bv: softmax-invariant, dropped
    float* out = (float*)d_out;

    cudaFuncSetAttribute(scores_mma_kernel,
                         cudaFuncAttributeMaxDynamicSharedMemorySize, SCORES_SMEM);

    conv_enc_kernel<<<(size_t)MROWS * EDIM / 2048, 256>>>(enc);
    conv_w1t_kernel<<<dim3(32, 32), dim3(32, 32)>>>(w1);
    qproj_kernel<<<dim3(BATCH, EDIM / 256), 256>>>(dec, w2, b2, b1);
    scores_mma_kernel<<<MROWS / 128, 256, SCORES_SMEM>>>(v);
    softmax_kernel<<<BATCH, 256>>>();
    context_part_kernel<<<dim3(EDIM / 256, NSC, BATCH), 128>>>();
    context_sum_kernel<<<BATCH * EDIM / 256, 256>>>(out);
}

// round 16
// speedup vs baseline: 1.1872x; 1.0116x over previous
#include <cuda_runtime.h>
#include <cuda_fp16.h>
#include <cstdint>

#define BATCH 32
#define SEQ   2048
#define EDIM  1024
#define MROWS (BATCH * SEQ)   // 65536
#define NSC   16              // context S-split chunks

// ---------------- device scratch (no allocations allowed) ----------------
__device__ float g_qb[BATCH * EDIM];
__device__ float g_scores[BATCH * SEQ];
__device__ float g_ctx_part[NSC * BATCH * EDIM];
__device__ __half g_a[(size_t)MROWS * EDIM];   // enc, fp16 (128 MB)
__device__ __half g_b[EDIM * EDIM];            // W1^T, fp16 [n][k]

// ---------------- PTX helpers ----------------
__device__ __forceinline__ uint32_t smem_u32(const void* p) {
    uint32_t a;
    asm("{ .reg .u64 t; cvta.to.shared.u64 t, %1; cvt.u32.u64 %0, t; }" : "=r"(a) : "l"(p));
    return a;
}
__device__ __forceinline__ void ldsm_x4(uint32_t* r, uint32_t addr) {
    asm volatile("ldmatrix.sync.aligned.m8n8.x4.shared.b16 {%0,%1,%2,%3}, [%4];"
                 : "=r"(r[0]), "=r"(r[1]), "=r"(r[2]), "=r"(r[3]) : "r"(addr));
}
__device__ __forceinline__ void mma_fp16(float* c, const uint32_t* a, const uint32_t* b) {
    asm volatile(
        "mma.sync.aligned.m16n8k16.row.col.f32.f16.f16.f32 "
        "{%0,%1,%2,%3}, {%4,%5,%6,%7}, {%8,%9}, {%0,%1,%2,%3};"
        : "+f"(c[0]), "+f"(c[1]), "+f"(c[2]), "+f"(c[3])
        : "r"(a[0]), "r"(a[1]), "r"(a[2]), "r"(a[3]), "r"(b[0]), "r"(b[1]));
}
__device__ __forceinline__ void cp16(uint32_t s, const void* g) {
    asm volatile("cp.async.cg.shared.global [%0], [%1], 16;" :: "r"(s), "l"(g));
}
#define CP_COMMIT() asm volatile("cp.async.commit_group;" ::: "memory")
#define CP_WAIT1()  asm volatile("cp.async.wait_group 1;" ::: "memory")
#define CP_WAIT0()  asm volatile("cp.async.wait_group 0;" ::: "memory")

#define MBAR_INIT(addr, cnt) \
    asm volatile("mbarrier.init.shared.b64 [%0], %1;" :: "r"(addr), "r"(cnt) : "memory")
#define MBAR_ARRIVE(addr) \
    asm volatile("mbarrier.arrive.shared.b64 _, [%0];" :: "r"(addr) : "memory")
__device__ __forceinline__ void mbar_wait(uint32_t addr, uint32_t parity) {
    asm volatile(
        "{\n\t.reg .pred P;\n\t"
        "WL_%=:\n\t"
        "mbarrier.try_wait.parity.acquire.cta.shared::cta.b64 P, [%0], %1, 0x989680;\n\t"
        "@!P bra WL_%=;\n\t}"
        :: "r"(addr), "r"(parity) : "memory");
}

__device__ __forceinline__ float fast_tanh(float x) {
    float e = __expf(2.0f * x);
    return 1.0f - 2.0f / (e + 1.0f);
}

// ---------------- K0a: convert enc -> fp16 ----------------
__global__ void conv_enc_kernel(const float* __restrict__ enc) {
    size_t base = ((size_t)blockIdx.x * 256 + threadIdx.x) * 8;
    float4 v0 = *reinterpret_cast<const float4*>(enc + base);
    float4 v1 = *reinterpret_cast<const float4*>(enc + base + 4);
    __half2 h[4];
    h[0] = __floats2half2_rn(v0.x, v0.y);
    h[1] = __floats2half2_rn(v0.z, v0.w);
    h[2] = __floats2half2_rn(v1.x, v1.y);
    h[3] = __floats2half2_rn(v1.z, v1.w);
    uint4 u;
    u.x = reinterpret_cast<uint32_t&>(h[0]); u.y = reinterpret_cast<uint32_t&>(h[1]);
    u.z = reinterpret_cast<uint32_t&>(h[2]); u.w = reinterpret_cast<uint32_t&>(h[3]);
    *reinterpret_cast<uint4*>(g_a + base) = u;
}

// ---------------- K0b: transpose + convert W1 -> B[n][k] fp16 ----------------
__global__ void conv_w1t_kernel(const float* __restrict__ w1) {
    __shared__ float t[32][33];
    int k0 = blockIdx.x * 32, n0 = blockIdx.y * 32;
    int tx = threadIdx.x, ty = threadIdx.y;
    t[ty][tx] = w1[(k0 + ty) * EDIM + n0 + tx];
    __syncthreads();
    g_b[(n0 + ty) * EDIM + k0 + tx] = __float2half_rn(t[tx][ty]);
}

// ---------------- K1: qb = dec@W2 + b2 + b1 ----------------
__global__ void qproj_kernel(const float* __restrict__ dec,
                             const float* __restrict__ w2,
                             const float* __restrict__ b2,
                             const float* __restrict__ b1) {
    __shared__ float sdec[EDIM];
    int b = blockIdx.x;
    int e = blockIdx.y * blockDim.x + threadIdx.x;
    for (int i = threadIdx.x; i < EDIM; i += blockDim.x)
        sdec[i] = dec[b * EDIM + i];
    __syncthreads();
    float acc = 0.f;
#pragma unroll 8
    for (int d = 0; d < EDIM; d++)
        acc += sdec[d] * w2[d * EDIM + e];
    g_qb[b * EDIM + e] = acc + b2[e] + b1[e];
}

// ---------------- K2: fp16 HMMA fused scores GEMM ----------------
// R15 champion geometry (256 thr, 4x2 warps of 32x64, BM=128, BN=128, BK=64,
// 3-stage ring, 2 CTAs/SM, mbarrier full/empty drift pipeline).
// Change vs R15: full-barrier arrivals 256 -> 8 (wait_group + syncwarp + lane0).
#define STG_BYTES 32768
#define A_OFF 0
#define B_OFF 16384
#define QV_OFF  (3 * STG_BYTES)               // 98304
#define MB_OFF  (QV_OFF + 2560)               // after s_q/s_v/s_sc
#define SCORES_SMEM (MB_OFF + 64)             // 100928

// rows are 128B (64 halves), 8 chunks of 16B, full XOR swizzle
__device__ __forceinline__ uint32_t swz_off(int r, int kc) {
    return (uint32_t)(r * 128 + ((kc ^ (r & 7)) << 4));
}

__global__ __launch_bounds__(256, 2) void scores_mma_kernel(const float* __restrict__ v) {
    extern __shared__ char sm[];
    const uint32_t sb = smem_u32(sm);
    const int tid = threadIdx.x;
    const int lane = tid & 31, wid = tid >> 5;
    const int wy = wid >> 1, wn = wid & 1;       // 4 x 2 warp grid, 32x64 tiles
    const int m0 = blockIdx.x * 128;
    const int b  = m0 >> 11;

    float* s_q  = reinterpret_cast<float*>(sm + QV_OFF);        // [2][128]
    float* s_v  = s_q + 256;                                    // [2][128]
    float* s_sc = s_v + 256;                                    // [128]
    const uint32_t mb_full  = sb + MB_OFF;       // 3 x 8B
    const uint32_t mb_empty = sb + MB_OFF + 24;  // 3 x 8B

    // ldmatrix lane invariants (verified R5..R15)
    const int a_mi = (lane & 7) + ((lane >> 3) & 1) * 8;
    const int a_kc = lane >> 4;                   // 0/1
    int a_row[2], a_swz[2];
#pragma unroll
    for (int mt = 0; mt < 2; mt++) {
        int r = wy * 32 + mt * 16 + a_mi;
        a_row[mt] = r * 128;
        a_swz[mt] = r & 7;
    }
    const int b_ni = (lane & 7) + ((lane >> 4) & 1) * 8;
    const int b_kc = (lane >> 3) & 1;
    int b_row[4], b_swz[4];
#pragma unroll
    for (int p = 0; p < 4; p++) {
        int n = wn * 64 + p * 16 + b_ni;
        b_row[p] = n * 128;
        b_swz[p] = n & 7;
    }

    // loader for global stage gs (np = gs>>4, ks = gs&15) into ring buffer bufidx
    auto load_stage = [&](int gs, int bufidx) {
        const int n0 = (gs >> 4) * 128, k0 = (gs & 15) * 64;
        const uint32_t base = sb + bufidx * STG_BYTES;
#pragma unroll
        for (int i = 0; i < 4; i++) {
            int c = tid + i * 256;               // 0..1023
            int row = c >> 3, kc = c & 7;
            uint32_t so = swz_off(row, kc);
            size_t ga = (size_t)(m0 + row) * EDIM + k0 + kc * 8;
            size_t gb = (size_t)(n0 + row) * EDIM + k0 + kc * 8;
            cp16(base + A_OFF + so, g_a + ga);
            cp16(base + B_OFF + so, g_b + gb);
        }
    };

    if (tid < 128) s_sc[tid] = 0.f;
    if (tid == 0) {
#pragma unroll
        for (int i = 0; i < 3; i++) {
            MBAR_INIT(mb_full + i * 8, 8);       // one arrive per warp per stage
            MBAR_INIT(mb_empty + i * 8, 8);      // one arrive per warp per stage
        }
    }
    __syncthreads();   // mbarriers + s_sc visible

    // prologue: stages 0 and 1 in flight (buffers 0, 1)
    load_stage(0, 0); CP_COMMIT();
    load_stage(1, 1); CP_COMMIT();

    int cbuf = 0, fp = 0;   // compute buffer + full-phase (flips when cbuf wraps)
    int lbuf = 2, ep = 0;   // load buffer + empty-phase (flips after waiting buf 2)

    for (int np = 0; np < 8; np++) {
        // double-buffered per-pass params (consumed in this np's epilogue;
        // parity-safe: warp drift bounded by empty backpressure << 17 stages)
        if (tid < 128) {
            const int n0 = np * 128;
            s_q[(np & 1) * 128 + tid] = g_qb[b * EDIM + n0 + tid];
            s_v[(np & 1) * 128 + tid] = v[n0 + tid];
        }

        float acc[2][8][4];
#pragma unroll
        for (int mt = 0; mt < 2; mt++)
#pragma unroll
            for (int nt = 0; nt < 8; nt++)
#pragma unroll
                for (int r = 0; r < 4; r++) acc[mt][nt][r] = 0.f;

        for (int ks = 0; ks < 16; ks++) {
            const int gs = np * 16 + ks;

            // A: own loads of stage gs complete; whole warp's done -> 1 arrive
            if (gs == 127) { CP_WAIT0(); } else { CP_WAIT1(); }
            __syncwarp();
            if (lane == 0) MBAR_ARRIVE(mb_full + cbuf * 8);

            // B: backpressure on ring reuse, then issue loads for gs+2
            if (gs + 2 < 128) {
                if (gs >= 1) {                   // first use of each buffer skips
                    mbar_wait(mb_empty + lbuf * 8, (uint32_t)ep);
                    if (lbuf == 2) ep ^= 1;
                }
                load_stage(gs + 2, lbuf);
                CP_COMMIT();
                lbuf = (lbuf == 2) ? 0 : lbuf + 1;
            }

            // C: wait all warps' loads of gs, compute, release buffer
            mbar_wait(mb_full + cbuf * 8, (uint32_t)fp);

            const uint32_t base = sb + cbuf * STG_BYTES;
#pragma unroll
            for (int kk = 0; kk < 4; kk++) {     // 4 x k16 within k64 stage
                uint32_t af[2][4];
#pragma unroll
                for (int mt = 0; mt < 2; mt++) {
                    uint32_t ao = (uint32_t)(a_row[mt] +
                        (((kk * 2 + a_kc) ^ a_swz[mt]) << 4));
                    ldsm_x4(af[mt], base + A_OFF + ao);
                }
#pragma unroll
                for (int p = 0; p < 4; p++) {
                    uint32_t bo = (uint32_t)(b_row[p] +
                        (((kk * 2 + b_kc) ^ b_swz[p]) << 4));
                    uint32_t bf[4];
                    ldsm_x4(bf, base + B_OFF + bo);
#pragma unroll
                    for (int mt = 0; mt < 2; mt++) {
                        mma_fp16(acc[mt][2 * p],     af[mt], bf);
                        mma_fp16(acc[mt][2 * p + 1], af[mt], bf + 2);
                    }
                }
            }
            if (lane == 0) MBAR_ARRIVE(mb_empty + cbuf * 8);
            if (cbuf == 2) { cbuf = 0; fp ^= 1; } else { cbuf++; }
        }

        // epilogue: tanh(acc + q) . v
        {
            const float* q = s_q + (np & 1) * 128;
            const float* w = s_v + (np & 1) * 128;
            float part[4] = {0.f, 0.f, 0.f, 0.f};
#pragma unroll
            for (int mt = 0; mt < 2; mt++)
#pragma unroll
                for (int nt = 0; nt < 8; nt++) {
                    int qi = wn * 64 + nt * 8 + 2 * (lane & 3);
                    float* c = acc[mt][nt];
                    part[mt * 2 + 0] += fast_tanh(c[0] + q[qi]) * w[qi]
                                      + fast_tanh(c[1] + q[qi + 1]) * w[qi + 1];
                    part[mt * 2 + 1] += fast_tanh(c[2] + q[qi]) * w[qi]
                                      + fast_tanh(c[3] + q[qi + 1]) * w[qi + 1];
                }
#pragma unroll
            for (int i = 0; i < 4; i++) {
                part[i] += __shfl_xor_sync(0xffffffffu, part[i], 1);
                part[i] += __shfl_xor_sync(0xffffffffu, part[i], 2);
            }
            if ((lane & 3) == 0) {
                int rbase = wy * 32 + (lane >> 2);
                atomicAdd(&s_sc[rbase],      part[0]);
                atomicAdd(&s_sc[rbase + 8],  part[1]);
                atomicAdd(&s_sc[rbase + 16], part[2]);
                atomicAdd(&s_sc[rbase + 24], part[3]);
            }
        }
    }

    __syncthreads();   // all epilogue atomics done
    if (tid < 128) g_scores[m0 + tid] = s_sc[tid];
}

// ---------------- K3+K4a fused: per-CTA softmax recompute + context partials ----------------
__global__ void context_part_kernel() {
    const int b = blockIdx.z;
    const int sc = blockIdx.y;
    const int tid = threadIdx.x;                     // 128 threads
    const int lane = tid & 31, wid = tid >> 5;
    const int e2 = blockIdx.x * 128 + tid;           // half2 column index
    const int rows = SEQ / NSC;                      // 128
    __shared__ float red[4];
    __shared__ float red2[4];
    __shared__ float s_at[128];

    // softmax stats over the full row (deterministic, identical in all CTAs of b)
    const float* srow = g_scores + b * SEQ;
    float vals[SEQ / 128];
#pragma unroll
    for (int i = 0; i < SEQ / 128; i++)
        vals[i] = srow[tid + i * 128];

    float m = vals[0];
#pragma unroll
    for (int i = 1; i < SEQ / 128; i++) m = fmaxf(m, vals[i]);
#pragma unroll
    for (int off = 16; off >= 1; off >>= 1)
        m = fmaxf(m, __shfl_xor_sync(0xffffffffu, m, off));
    if (lane == 0) red[wid] = m;
    __syncthreads();
    float bm = fmaxf(fmaxf(red[0], red[1]), fmaxf(red[2], red[3]));

    float sum = 0.f;
#pragma unroll
    for (int i = 0; i < SEQ / 128; i++)
        sum += __expf(vals[i] - bm);
#pragma unroll
    for (int off = 16; off >= 1; off >>= 1)
        sum += __shfl_xor_sync(0xffffffffu, sum, off);
    if (lane == 0) red2[wid] = sum;
    __syncthreads();
    float inv = 1.0f / (red2[0] + red2[1] + red2[2] + red2[3]);

    // attention weights for this CTA's row slice
    s_at[tid] = __expf(srow[sc * rows + tid] - bm) * inv;
    __syncthreads();

    const __half2* A = reinterpret_cast<const __half2*>(g_a)
                     + (size_t)(b * SEQ + sc * rows) * (EDIM / 2) + e2;
    float ax = 0.f, ay = 0.f;
#pragma unroll 8
    for (int s = 0; s < rows; s++) {
        float w = s_at[s];
        float2 x = __half22float2(A[(size_t)s * (EDIM / 2)]);
        ax = fmaf(w, x.x, ax);
        ay = fmaf(w, x.y, ay);
    }
    float2* dst = reinterpret_cast<float2*>(
        g_ctx_part + ((size_t)sc * BATCH + b) * EDIM) + e2;
    *dst = make_float2(ax, ay);
}

// ---------------- K4b: sum partials ----------------
__global__ void context_sum_kernel(float* __restrict__ out) {
    const int i = blockIdx.x * 256 + threadIdx.x;
    float a = 0.f;
#pragma unroll
    for (int sc = 0; sc < NSC; sc++)
        a += g_ctx_part[(size_t)sc * BATCH * EDIM + i];
    out[i] = a;
}

// ---------------- launch ----------------
extern "C" void kernel_launch(void* const* d_in, const int* in_sizes, int n_in,
                              void* d_out, int out_size) {
    const float* enc = (const float*)d_in[0];
    const float* dec = (const float*)d_in[1];
    const float* w1  = (const float*)d_in[2];
    const float* b1  = (const float*)d_in[3];
    const float* w2  = (const float*)d_in[4];
    const float* b2  = (const float*)d_in[5];
    const float* v   = (const float*)d_in[6];
    // d_in[7] = bv: softmax-invariant, dropped
    float* out = (float*)d_out;

    cudaFuncSetAttribute(scores_mma_kernel,
                         cudaFuncAttributeMaxDynamicSharedMemorySize, SCORES_SMEM);

    conv_enc_kernel<<<(size_t)MROWS * EDIM / 2048, 256>>>(enc);
    conv_w1t_kernel<<<dim3(32, 32), dim3(32, 32)>>>(w1);
    qproj_kernel<<<dim3(BATCH, EDIM / 256), 256>>>(dec, w2, b2, b1);
    scores_mma_kernel<<<MROWS / 128, 256, SCORES_SMEM>>>(v);
    context_part_kernel<<<dim3(EDIM / 256, NSC, BATCH), 128>>>();
    context_sum_kernel<<<BATCH * EDIM / 256, 256>>>(out);
}